// round 14
// baseline (speedup 1.0000x reference)
#include <cuda_runtime.h>
#include <cuda_bf16.h>
#include <math.h>
#include <stdint.h>

// Problem constants
#define S_LEN 2048
#define BATCH 2
#define EMB   2048
#define HEADS 32
#define HDIM  64
#define MROWS (S_LEN * BATCH)          // 4096
#define QKV_N (3 * EMB)                // 6144
#define KDIM  2048
#define NIT_T 64                       // 2048 / 32 (BK=32 fp32)
#define MASK_NEG (-66504.0f)

// ---------------------------------------------------------------------------
// Scratch (static device globals)
// ---------------------------------------------------------------------------
__device__ float g_ctx[(size_t)MROWS * EMB];                   // [4096, 2048]
__device__ float g_hsr[(size_t)MROWS * EMB];                   // tf32-rounded hs

__device__ float g_Btq[(size_t)QKV_N * KDIM];                  // qkv_w^T (tf32-rounded)
__device__ float g_Bto[(size_t)EMB   * KDIM];                  // out_w^T (tf32-rounded)

#define QKVLEN ((size_t)BATCH * HEADS * S_LEN * HDIM)
__device__ __nv_bfloat16 g_qb [QKVLEN];   // rope(Q) * 0.125, bf16
__device__ __nv_bfloat16 g_kb [QKVLEN];   // rope(K), bf16
__device__ __nv_bfloat16 g_vhb[QKVLEN];   // V hi
__device__ __nv_bfloat16 g_vlb[QKVLEN];   // V lo

// ---------------------------------------------------------------------------
// Helpers (sm_80-era PTX — legal at compute_103)
// ---------------------------------------------------------------------------
__device__ __forceinline__ uint32_t smem_u32(const void* p) {
    uint32_t a;
    asm("{ .reg .u64 t; cvta.to.shared.u64 t, %1; cvt.u32.u64 %0, t; }" : "=r"(a) : "l"(p));
    return a;
}
__device__ __forceinline__ void cp16(uint32_t saddr, const void* g) {
    asm volatile("cp.async.cg.shared.global [%0], [%1], 16;" :: "r"(saddr), "l"(g) : "memory");
}
__device__ __forceinline__ void cp_commit() {
    asm volatile("cp.async.commit_group;" ::: "memory");
}
__device__ __forceinline__ uint32_t sw128(uint32_t off) {
    return off ^ ((off >> 3) & 0x70);
}
__device__ __forceinline__ float tf32r(float x) {   // round-to-nearest tf32
    uint32_t u;
    asm("cvt.rna.tf32.f32 %0, %1;" : "=r"(u) : "f"(x));
    return __uint_as_float(u);
}

#define LDSM4(r, addr) \
    asm volatile("ldmatrix.sync.aligned.m8n8.x4.shared.b16 {%0,%1,%2,%3}, [%4];" \
                 : "=r"((r)[0]), "=r"((r)[1]), "=r"((r)[2]), "=r"((r)[3]) : "r"(addr))

#define LDSM4T(r, addr) \
    asm volatile("ldmatrix.sync.aligned.m8n8.x4.trans.shared.b16 {%0,%1,%2,%3}, [%4];" \
                 : "=r"((r)[0]), "=r"((r)[1]), "=r"((r)[2]), "=r"((r)[3]) : "r"(addr))

__device__ __forceinline__ void mma_bf16(float* d, const uint32_t* a, uint32_t b0, uint32_t b1) {
    asm volatile(
        "mma.sync.aligned.m16n8k16.row.col.f32.bf16.bf16.f32 "
        "{%0,%1,%2,%3}, {%4,%5,%6,%7}, {%8,%9}, {%0,%1,%2,%3};"
        : "+f"(d[0]), "+f"(d[1]), "+f"(d[2]), "+f"(d[3])
        : "r"(a[0]), "r"(a[1]), "r"(a[2]), "r"(a[3]), "r"(b0), "r"(b1));
}

__device__ __forceinline__ void mma_tf32(float* d, const uint32_t* a, uint32_t b0, uint32_t b1) {
    asm volatile(
        "mma.sync.aligned.m16n8k8.row.col.f32.tf32.tf32.f32 "
        "{%0,%1,%2,%3}, {%4,%5,%6,%7}, {%8,%9}, {%0,%1,%2,%3};"
        : "+f"(d[0]), "+f"(d[1]), "+f"(d[2]), "+f"(d[3])
        : "r"(a[0]), "r"(a[1]), "r"(a[2]), "r"(a[3]), "r"(b0), "r"(b1));
}

__device__ __forceinline__ uint32_t packlo(float a, float b, float& ra, float& rb) {
    __nv_bfloat162 h = __floats2bfloat162_rn(a, b);
    ra = a - __bfloat162float(__low2bfloat16(h));
    rb = b - __bfloat162float(__high2bfloat16(h));
    return *reinterpret_cast<uint32_t*>(&h);
}
__device__ __forceinline__ uint32_t packb(float a, float b) {
    __nv_bfloat162 h = __floats2bfloat162_rn(a, b);
    return *reinterpret_cast<uint32_t*>(&h);
}

// ---------------------------------------------------------------------------
// TF32 HMMA GEMM:  C[M=4096, N] = A[M, 2048] @ Bt[N, 2048]^T + bias
// Proven R5/R10 schedule: CTA 128x128, BK=32, 3-stage cp.async, 8 warps
// (2x4, 64x32 warp tile), 2 CTAs/SM. Operands pre-rounded to tf32 (RNA).
// ROPE=true: fused epilogue — stage C in smem, apply bias + RoPE + bf16
// split, write g_qb/g_kb/g_vhb/g_vlb directly (CTA tile = 2 full heads).
// ROPE=false: plain bias epilogue to C.
// ---------------------------------------------------------------------------
#define GEMM_SMEM (3 * 32768)

template<bool ROPE>
__global__ __launch_bounds__(256, 2)
void gemm_tf32(int N,
               const float* __restrict__ A,
               const float* __restrict__ Bt,
               const float* __restrict__ bias,
               float* __restrict__ C) {
    extern __shared__ char sm[];
    const int tid = threadIdx.x;
    const int wid = tid >> 5;
    const int lid = tid & 31;
    const int M0 = blockIdx.y * 128;
    const int N0 = blockIdx.x * 128;
    const uint32_t sbase = smem_u32(sm);

    const int lrow  = tid >> 1;
    const int lhalf = (tid & 1) * 64;
    const uint32_t soff = (uint32_t)lrow * 128u + (uint32_t)lhalf;
    const char* Ag = (const char*)(A  + (size_t)(M0 + lrow) * KDIM) + lhalf;
    const char* Bg = (const char*)(Bt + (size_t)(N0 + lrow) * KDIM) + lhalf;

    const int wm = (wid & 1) * 64;
    const int wn = (wid >> 1) * 32;
    const int a_r  = wm + (lid & 15);
    const int ldsm_cb = (lid >> 4) * 16;
    const int b_r  = wn + (lid & 15);

    float acc[4][4][4];
#pragma unroll
    for (int i = 0; i < 4; ++i)
#pragma unroll
        for (int j = 0; j < 4; ++j)
#pragma unroll
            for (int q = 0; q < 4; ++q) acc[i][j][q] = 0.0f;

#pragma unroll
    for (int s = 0; s < 2; ++s) {
        uint32_t ab = sbase + s * 32768u;
        uint32_t bb = ab + 16384u;
        const char* ag = Ag + s * 128;
        const char* bg = Bg + s * 128;
#pragma unroll
        for (int i = 0; i < 4; ++i) {
            cp16(ab + sw128(soff + i * 16), ag + i * 16);
            cp16(bb + sw128(soff + i * 16), bg + i * 16);
        }
        cp_commit();
    }

#pragma unroll 1
    for (int it = 0; it < NIT_T; ++it) {
        if (it + 1 < NIT_T) asm volatile("cp.async.wait_group 1;" ::: "memory");
        else                asm volatile("cp.async.wait_group 0;" ::: "memory");
        __syncthreads();

        if (it + 2 < NIT_T) {
            int s1 = (it + 2) % 3;
            uint32_t ab = sbase + s1 * 32768u;
            uint32_t bb = ab + 16384u;
            const char* ag = Ag + (size_t)(it + 2) * 128;
            const char* bg = Bg + (size_t)(it + 2) * 128;
#pragma unroll
            for (int i = 0; i < 4; ++i) {
                cp16(ab + sw128(soff + i * 16), ag + i * 16);
                cp16(bb + sw128(soff + i * 16), bg + i * 16);
            }
            cp_commit();
        }

        const int s = it % 3;
        const uint32_t ab = sbase + s * 32768u;
        const uint32_t bb = ab + 16384u;

#pragma unroll
        for (int k8 = 0; k8 < 4; ++k8) {
            uint32_t Ar[4][4];
            uint32_t Br[2][4];
#pragma unroll
            for (int i = 0; i < 4; ++i)
                LDSM4(Ar[i], ab + sw128((uint32_t)(a_r + i * 16) * 128u + k8 * 32 + ldsm_cb));
#pragma unroll
            for (int j2 = 0; j2 < 2; ++j2)
                LDSM4(Br[j2], bb + sw128((uint32_t)(b_r + j2 * 16) * 128u + k8 * 32 + ldsm_cb));
#pragma unroll
            for (int i = 0; i < 4; ++i)
#pragma unroll
                for (int j = 0; j < 4; ++j)
                    mma_tf32(acc[i][j], Ar[i],
                             Br[j >> 1][(j & 1)], Br[j >> 1][(j & 1) + 2]);
        }
    }

    const int fr = lid >> 2;
    const int fc = (lid & 3) * 2;

    if (!ROPE) {
        // plain epilogue: bias + fp32 store
#pragma unroll
        for (int j = 0; j < 4; ++j) {
            const int col = N0 + wn + j * 8 + fc;
            const float bx = bias[col];
            const float by = bias[col + 1];
#pragma unroll
            for (int i = 0; i < 4; ++i) {
                const int row = M0 + wm + i * 16 + fr;
                float2 v0 = make_float2(acc[i][j][0] + bx, acc[i][j][1] + by);
                float2 v1 = make_float2(acc[i][j][2] + bx, acc[i][j][3] + by);
                *reinterpret_cast<float2*>(C + (size_t)row * N + col) = v0;
                *reinterpret_cast<float2*>(C + (size_t)(row + 8) * N + col) = v1;
            }
        }
        return;
    }

    // ---- fused RoPE/split epilogue ----
    __syncthreads();  // all warps done with the smem stages
    float* Cs = reinterpret_cast<float*>(sm);   // 128 x 129 fp32 staging

#pragma unroll
    for (int j = 0; j < 4; ++j) {
        const int lc = wn + j * 8 + fc;
        const float bx = bias[N0 + lc];
        const float by = bias[N0 + lc + 1];
#pragma unroll
        for (int i = 0; i < 4; ++i) {
            const int lr = wm + i * 16 + fr;
            Cs[lr * 129 + lc]           = acc[i][j][0] + bx;
            Cs[lr * 129 + lc + 1]       = acc[i][j][1] + by;
            Cs[(lr + 8) * 129 + lc]     = acc[i][j][2] + bx;
            Cs[(lr + 8) * 129 + lc + 1] = acc[i][j][3] + by;
        }
    }
    __syncthreads();

    // thread -> (row, head). 128 rows x 2 heads, 64 cols each.
    const int row = tid & 127;
    const int head = tid >> 7;
    const int mg = M0 + row;
    const int srow = mg >> 1;          // sequence position
    const int b = mg & 1;
    const int sec = N0 >> 11;          // 0=Q, 1=K, 2=V
    const int hg = ((N0 & 2047) >> 6) + head;
    const float* xs = Cs + row * 129 + head * 64;

    size_t o = ((size_t)(b * HEADS + hg) * S_LEN + srow) * HDIM;

    if (sec < 2) {
        __nv_bfloat16* outp = (sec == 0) ? g_qb : g_kb;
        const float qscale = (sec == 0) ? 0.125f : 1.0f;
#pragma unroll
        for (int ha = 0; ha < 2; ++ha) {
            const int d0 = ha * 16;
            float xl[16], xh[16];
#pragma unroll
            for (int i = 0; i < 16; ++i) {
                xl[i] = xs[d0 + i];
                xh[i] = xs[d0 + 32 + i];
            }
#pragma unroll
            for (int i = 0; i < 16; ++i) {
                float invf = __expf(-0.28782252f * (float)(d0 + i));
                float sn, cs;
                sincosf((float)srow * invf, &sn, &cs);
                float a0 = xl[i], a1 = xh[i];
                xl[i] = (a0 * cs - a1 * sn) * qscale;
                xh[i] = (a1 * cs + a0 * sn) * qscale;
            }
            uint32_t pk[8];
#pragma unroll
            for (int i = 0; i < 8; ++i) pk[i] = packb(xl[2 * i], xl[2 * i + 1]);
            uint4* dl = reinterpret_cast<uint4*>(outp + o + d0);
            dl[0] = make_uint4(pk[0], pk[1], pk[2], pk[3]);
            dl[1] = make_uint4(pk[4], pk[5], pk[6], pk[7]);
#pragma unroll
            for (int i = 0; i < 8; ++i) pk[i] = packb(xh[2 * i], xh[2 * i + 1]);
            uint4* dh = reinterpret_cast<uint4*>(outp + o + d0 + 32);
            dh[0] = make_uint4(pk[0], pk[1], pk[2], pk[3]);
            dh[1] = make_uint4(pk[4], pk[5], pk[6], pk[7]);
        }
    } else {
        // V: split hi/lo
#pragma unroll
        for (int qa = 0; qa < 4; ++qa) {
            const int d0 = qa * 16;
            float xv[16];
#pragma unroll
            for (int i = 0; i < 16; ++i) xv[i] = xs[d0 + i];
            uint32_t ph[8], pl[8];
#pragma unroll
            for (int i = 0; i < 8; ++i) {
                float r0, r1;
                ph[i] = packlo(xv[2 * i], xv[2 * i + 1], r0, r1);
                pl[i] = packb(r0, r1);
            }
            uint4* dh = reinterpret_cast<uint4*>(g_vhb + o + d0);
            dh[0] = make_uint4(ph[0], ph[1], ph[2], ph[3]);
            dh[1] = make_uint4(ph[4], ph[5], ph[6], ph[7]);
            uint4* dl = reinterpret_cast<uint4*>(g_vlb + o + d0);
            dl[0] = make_uint4(pl[0], pl[1], pl[2], pl[3]);
            dl[1] = make_uint4(pl[4], pl[5], pl[6], pl[7]);
        }
    }
}

// ---------------------------------------------------------------------------
// Weight transpose + RNA tf32 rounding: fp32 [2048, Ncols] -> [Ncols, 2048]
// ---------------------------------------------------------------------------
__global__ __launch_bounds__(1024)
void transpose_kernel(const float* __restrict__ src, float* __restrict__ dst, int Ncols) {
    __shared__ float tile[32][33];
    const int k0 = blockIdx.y * 32;
    const int n0 = blockIdx.x * 32;
    const int tx = threadIdx.x;
    const int ty = threadIdx.y;
    tile[ty][tx] = src[(size_t)(k0 + ty) * Ncols + n0 + tx];
    __syncthreads();
    dst[(size_t)(n0 + ty) * KDIM + k0 + tx] = tf32r(tile[tx][ty]);
}

// A pre-round: fp32 -> RNA tf32-valued fp32
__global__ __launch_bounds__(256)
void roundA_kernel(const float* __restrict__ src, float* __restrict__ dst) {
    size_t i = ((size_t)blockIdx.x * 256 + threadIdx.x) * 4;
    float4 v = *reinterpret_cast<const float4*>(src + i);
    v.x = tf32r(v.x); v.y = tf32r(v.y); v.z = tf32r(v.z); v.w = tf32r(v.w);
    *reinterpret_cast<float4*>(dst + i) = v;
}

// ---------------------------------------------------------------------------
// HMMA flash attention (R10 version; ctx stores RNA-rounded to tf32)
// ---------------------------------------------------------------------------
#define ATTN_SMEM 65536

__global__ __launch_bounds__(256, 2)
void attn_kernel() {
    extern __shared__ char smc[];
    const uint32_t sQ = smem_u32(smc);

    const int bh = blockIdx.y;
    const int qt = 15 - (int)blockIdx.x;
    const int q0 = qt * 128;
    const int t  = threadIdx.x;
    const int w  = t >> 5;
    const int lid = t & 31;

    const __nv_bfloat16* Qg  = g_qb  + (size_t)bh * S_LEN * HDIM;
    const __nv_bfloat16* Kg  = g_kb  + (size_t)bh * S_LEN * HDIM;
    const __nv_bfloat16* Vhg = g_vhb + (size_t)bh * S_LEN * HDIM;
    const __nv_bfloat16* Vlg = g_vlb + (size_t)bh * S_LEN * HDIM;

    {
        const int row = t >> 1;
        const int half = (t & 1) * 64;
        const char* src = (const char*)(Qg + (size_t)(q0 + row) * HDIM) + half;
#pragma unroll
        for (int i = 0; i < 4; ++i)
            cp16(sQ + sw128((uint32_t)row * 128u + half + i * 16), src + i * 16);
    }
    {
        const int row = t >> 2;
        const int qo = (t & 3) * 32;
        const uint32_t so = sw128((uint32_t)row * 128u + qo);
        const uint32_t so2 = sw128((uint32_t)row * 128u + qo + 16);
        const char* kg = (const char*)(Kg + (size_t)row * HDIM) + qo;
        const char* vh = (const char*)(Vhg + (size_t)row * HDIM) + qo;
        const char* vl = (const char*)(Vlg + (size_t)row * HDIM) + qo;
        uint32_t bK = sQ + 16384u;
        cp16(bK + so, kg);           cp16(bK + so2, kg + 16);
        cp16(bK + 8192u + so, vh);   cp16(bK + 8192u + so2, vh + 16);
        cp16(bK + 16384u + so, vl);  cp16(bK + 16384u + so2, vl + 16);
    }
    cp_commit();

    float oc[8][4];
#pragma unroll
    for (int jn = 0; jn < 8; ++jn)
#pragma unroll
        for (int q = 0; q < 4; ++q) oc[jn][q] = 0.0f;
    float m[2] = {-1e30f, -1e30f};
    float l[2] = {0.0f, 0.0f};

    const int nkt = 2 * qt + 2;
#pragma unroll 1
    for (int kt = 0; kt < nkt; ++kt) {
        if (kt + 1 < nkt) {
            const int k1 = (kt + 1) * 64;
            const int row = t >> 2;
            const int qo = (t & 3) * 32;
            const uint32_t so = sw128((uint32_t)row * 128u + qo);
            const uint32_t so2 = sw128((uint32_t)row * 128u + qo + 16);
            const char* kg = (const char*)(Kg + (size_t)(k1 + row) * HDIM) + qo;
            const char* vh = (const char*)(Vhg + (size_t)(k1 + row) * HDIM) + qo;
            const char* vl = (const char*)(Vlg + (size_t)(k1 + row) * HDIM) + qo;
            uint32_t bK = sQ + 16384u + ((kt + 1) & 1) * 24576u;
            cp16(bK + so, kg);           cp16(bK + so2, kg + 16);
            cp16(bK + 8192u + so, vh);   cp16(bK + 8192u + so2, vh + 16);
            cp16(bK + 16384u + so, vl);  cp16(bK + 16384u + so2, vl + 16);
            cp_commit();
            asm volatile("cp.async.wait_group 1;" ::: "memory");
        } else {
            asm volatile("cp.async.wait_group 0;" ::: "memory");
        }
        __syncthreads();

        const uint32_t bK  = sQ + 16384u + (kt & 1) * 24576u;
        const uint32_t bVh = bK + 8192u;
        const uint32_t bVl = bK + 16384u;
        const int k0 = kt * 64;

        float sc[8][4];
#pragma unroll
        for (int jn = 0; jn < 8; ++jn)
#pragma unroll
            for (int q = 0; q < 4; ++q) sc[jn][q] = 0.0f;

#pragma unroll
        for (int k4 = 0; k4 < 4; ++k4) {
            uint32_t QA[4];
            LDSM4(QA, sQ + sw128((uint32_t)(w * 16 + (lid & 15)) * 128u + k4 * 32 + (lid >> 4) * 16));
#pragma unroll
            for (int j2 = 0; j2 < 4; ++j2) {
                uint32_t KB[4];
                LDSM4(KB, bK + sw128((uint32_t)((lid & 7) + ((lid >> 4) << 3) + j2 * 16) * 128u
                                     + k4 * 32 + ((lid >> 3) & 1) * 16));
                mma_bf16(sc[j2 * 2 + 0], QA, KB[0], KB[1]);
                mma_bf16(sc[j2 * 2 + 1], QA, KB[2], KB[3]);
            }
        }

        if (k0 + 63 > q0 + w * 16) {
            const int rlo = q0 + w * 16 + (lid >> 2);
#pragma unroll
            for (int jn = 0; jn < 8; ++jn) {
                const int cb = k0 + jn * 8 + (lid & 3) * 2;
#pragma unroll
                for (int q = 0; q < 4; ++q) {
                    const int colg = cb + (q & 1);
                    const int rowg = rlo + (q >> 1) * 8;
                    if (colg > rowg) sc[jn][q] += MASK_NEG;
                }
            }
        }

#pragma unroll
        for (int hh = 0; hh < 2; ++hh) {
            float mt = sc[0][hh * 2];
#pragma unroll
            for (int jn = 0; jn < 8; ++jn)
                mt = fmaxf(mt, fmaxf(sc[jn][hh * 2], sc[jn][hh * 2 + 1]));
            mt = fmaxf(mt, __shfl_xor_sync(0xffffffffu, mt, 1));
            mt = fmaxf(mt, __shfl_xor_sync(0xffffffffu, mt, 2));

            const float mn = fmaxf(m[hh], mt);
            const float corr = __expf(m[hh] - mn);
            float ps = 0.0f;
#pragma unroll
            for (int jn = 0; jn < 8; ++jn) {
                float p0 = __expf(sc[jn][hh * 2] - mn);
                float p1 = __expf(sc[jn][hh * 2 + 1] - mn);
                sc[jn][hh * 2] = p0;
                sc[jn][hh * 2 + 1] = p1;
                ps += p0 + p1;
            }
            ps += __shfl_xor_sync(0xffffffffu, ps, 1);
            ps += __shfl_xor_sync(0xffffffffu, ps, 2);
            l[hh] = l[hh] * corr + ps;
            m[hh] = mn;
#pragma unroll
            for (int jn = 0; jn < 8; ++jn) {
                oc[jn][hh * 2] *= corr;
                oc[jn][hh * 2 + 1] *= corr;
            }
        }

#pragma unroll
        for (int k4 = 0; k4 < 4; ++k4) {
            uint32_t PhA[4], PlA[4];
            {
                float r0, r1, r2, r3, r4, r5, r6, r7;
                PhA[0] = packlo(sc[2 * k4][0], sc[2 * k4][1], r0, r1);
                PhA[1] = packlo(sc[2 * k4][2], sc[2 * k4][3], r2, r3);
                PhA[2] = packlo(sc[2 * k4 + 1][0], sc[2 * k4 + 1][1], r4, r5);
                PhA[3] = packlo(sc[2 * k4 + 1][2], sc[2 * k4 + 1][3], r6, r7);
                PlA[0] = packb(r0, r1);
                PlA[1] = packb(r2, r3);
                PlA[2] = packb(r4, r5);
                PlA[3] = packb(r6, r7);
            }
#pragma unroll
            for (int j2 = 0; j2 < 4; ++j2) {
                uint32_t VhB[4], VlB[4];
                LDSM4T(VhB, bVh + sw128((uint32_t)(k4 * 16 + (lid & 15)) * 128u + j2 * 32 + (lid >> 4) * 16));
                LDSM4T(VlB, bVl + sw128((uint32_t)(k4 * 16 + (lid & 15)) * 128u + j2 * 32 + (lid >> 4) * 16));
                mma_bf16(oc[j2 * 2 + 0], PhA, VhB[0], VhB[1]);
                mma_bf16(oc[j2 * 2 + 1], PhA, VhB[2], VhB[3]);
                mma_bf16(oc[j2 * 2 + 0], PhA, VlB[0], VlB[1]);
                mma_bf16(oc[j2 * 2 + 1], PhA, VlB[2], VlB[3]);
                mma_bf16(oc[j2 * 2 + 0], PlA, VhB[0], VhB[1]);
                mma_bf16(oc[j2 * 2 + 1], PlA, VhB[2], VhB[3]);
            }
        }
        __syncthreads();
    }

    const int b = bh >> 5;
    const int h = bh & 31;
#pragma unroll
    for (int hh = 0; hh < 2; ++hh) {
        const int row = q0 + w * 16 + (lid >> 2) + hh * 8;
        const float invl = 1.0f / l[hh];
        float* dst = g_ctx + (size_t)(row * BATCH + b) * EMB + h * HDIM;
#pragma unroll
        for (int jn = 0; jn < 8; ++jn) {
            float2 v = make_float2(tf32r(oc[jn][hh * 2] * invl),
                                   tf32r(oc[jn][hh * 2 + 1] * invl));
            *reinterpret_cast<float2*>(dst + jn * 8 + (lid & 3) * 2) = v;
        }
    }
}

// ---------------------------------------------------------------------------
// Launch
// ---------------------------------------------------------------------------
extern "C" void kernel_launch(void* const* d_in, const int* in_sizes, int n_in,
                              void* d_out, int out_size) {
    const float* hs    = (const float*)d_in[0];
    const float* qkv_w = (const float*)d_in[1];
    const float* qkv_b = (const float*)d_in[2];
    const float* out_w = (const float*)d_in[3];
    const float* out_b = (const float*)d_in[4];
    float* out = (float*)d_out;

    cudaFuncSetAttribute(gemm_tf32<true>,  cudaFuncAttributeMaxDynamicSharedMemorySize, GEMM_SMEM);
    cudaFuncSetAttribute(gemm_tf32<false>, cudaFuncAttributeMaxDynamicSharedMemorySize, GEMM_SMEM);
    cudaFuncSetAttribute(attn_kernel, cudaFuncAttributeMaxDynamicSharedMemorySize, ATTN_SMEM);

    float *ctx, *hsr, *Btq, *Bto;
    cudaGetSymbolAddress((void**)&ctx, g_ctx);
    cudaGetSymbolAddress((void**)&hsr, g_hsr);
    cudaGetSymbolAddress((void**)&Btq, g_Btq);
    cudaGetSymbolAddress((void**)&Bto, g_Bto);

    // Weight transposes (RNA-rounded to tf32 values)
    {
        dim3 blk(32, 32);
        transpose_kernel<<<dim3(QKV_N / 32, KDIM / 32), blk>>>(qkv_w, Btq, QKV_N);
        transpose_kernel<<<dim3(EMB / 32, KDIM / 32), blk>>>(out_w, Bto, EMB);
    }
    // Pre-round activations (RNA -> unbiased tf32)
    roundA_kernel<<<(MROWS * EMB) / 1024, 256>>>(hs, hsr);

    // 1. QKV projection with fused bias + RoPE + bf16 split epilogue
    gemm_tf32<true><<<dim3(QKV_N / 128, MROWS / 128), 256, GEMM_SMEM>>>(
        QKV_N, hsr, Btq, qkv_b, nullptr);

    // 2. Causal attention (HMMA flash); ctx RNA-rounded at store
    attn_kernel<<<dim3(S_LEN / 128, BATCH * HEADS), 256, ATTN_SMEM>>>();

    // 3. Output projection
    gemm_tf32<false><<<dim3(EMB / 128, MROWS / 128), 256, GEMM_SMEM>>>(
        EMB, ctx, Bto, out_b, out);
}

// round 15
// speedup vs baseline: 1.7185x; 1.7185x over previous
#include <cuda_runtime.h>
#include <cuda_bf16.h>
#include <cuda_fp16.h>
#include <math.h>
#include <stdint.h>

// Problem constants
#define S_LEN 2048
#define BATCH 2
#define EMB   2048
#define HEADS 32
#define HDIM  64
#define MROWS (S_LEN * BATCH)          // 4096
#define QKV_N (3 * EMB)                // 6144
#define KDIM  2048
#define NIT_H 32                       // 2048 / 64 (BK=64 fp16)
#define MASK_NEG (-66504.0f)

// ---------------------------------------------------------------------------
// Scratch (static device globals)
// ---------------------------------------------------------------------------
__device__ __half g_ctx[(size_t)MROWS * EMB];                  // attention out, fp16
__device__ __half g_hsh[(size_t)MROWS * EMB];                  // hs -> fp16

__device__ __half g_Btq[(size_t)QKV_N * KDIM];                 // qkv_w^T fp16
__device__ __half g_Bto[(size_t)EMB   * KDIM];                 // out_w^T fp16

#define QKVLEN ((size_t)BATCH * HEADS * S_LEN * HDIM)
__device__ __nv_bfloat16 g_qb [QKVLEN];   // rope(Q) * 0.125, bf16
__device__ __nv_bfloat16 g_kb [QKVLEN];   // rope(K), bf16
__device__ __nv_bfloat16 g_vhb[QKVLEN];   // V hi
__device__ __nv_bfloat16 g_vlb[QKVLEN];   // V lo

// ---------------------------------------------------------------------------
// Helpers (sm_80-era PTX — legal at compute_103)
// ---------------------------------------------------------------------------
__device__ __forceinline__ uint32_t smem_u32(const void* p) {
    uint32_t a;
    asm("{ .reg .u64 t; cvta.to.shared.u64 t, %1; cvt.u32.u64 %0, t; }" : "=r"(a) : "l"(p));
    return a;
}
__device__ __forceinline__ void cp16(uint32_t saddr, const void* g) {
    asm volatile("cp.async.cg.shared.global [%0], [%1], 16;" :: "r"(saddr), "l"(g) : "memory");
}
__device__ __forceinline__ void cp_commit() {
    asm volatile("cp.async.commit_group;" ::: "memory");
}
__device__ __forceinline__ uint32_t sw128(uint32_t off) {
    return off ^ ((off >> 3) & 0x70);
}

#define LDSM4(r, addr) \
    asm volatile("ldmatrix.sync.aligned.m8n8.x4.shared.b16 {%0,%1,%2,%3}, [%4];" \
                 : "=r"((r)[0]), "=r"((r)[1]), "=r"((r)[2]), "=r"((r)[3]) : "r"(addr))

#define LDSM4T(r, addr) \
    asm volatile("ldmatrix.sync.aligned.m8n8.x4.trans.shared.b16 {%0,%1,%2,%3}, [%4];" \
                 : "=r"((r)[0]), "=r"((r)[1]), "=r"((r)[2]), "=r"((r)[3]) : "r"(addr))

__device__ __forceinline__ void mma_bf16(float* d, const uint32_t* a, uint32_t b0, uint32_t b1) {
    asm volatile(
        "mma.sync.aligned.m16n8k16.row.col.f32.bf16.bf16.f32 "
        "{%0,%1,%2,%3}, {%4,%5,%6,%7}, {%8,%9}, {%0,%1,%2,%3};"
        : "+f"(d[0]), "+f"(d[1]), "+f"(d[2]), "+f"(d[3])
        : "r"(a[0]), "r"(a[1]), "r"(a[2]), "r"(a[3]), "r"(b0), "r"(b1));
}

__device__ __forceinline__ void mma_f16(float* d, const uint32_t* a, uint32_t b0, uint32_t b1) {
    asm volatile(
        "mma.sync.aligned.m16n8k16.row.col.f32.f16.f16.f32 "
        "{%0,%1,%2,%3}, {%4,%5,%6,%7}, {%8,%9}, {%0,%1,%2,%3};"
        : "+f"(d[0]), "+f"(d[1]), "+f"(d[2]), "+f"(d[3])
        : "r"(a[0]), "r"(a[1]), "r"(a[2]), "r"(a[3]), "r"(b0), "r"(b1));
}

__device__ __forceinline__ uint32_t packlo(float a, float b, float& ra, float& rb) {
    __nv_bfloat162 h = __floats2bfloat162_rn(a, b);
    ra = a - __bfloat162float(__low2bfloat16(h));
    rb = b - __bfloat162float(__high2bfloat16(h));
    return *reinterpret_cast<uint32_t*>(&h);
}
__device__ __forceinline__ uint32_t packb(float a, float b) {
    __nv_bfloat162 h = __floats2bfloat162_rn(a, b);
    return *reinterpret_cast<uint32_t*>(&h);
}

// ---------------------------------------------------------------------------
// FP16 HMMA GEMM:  C[M=4096, N] = A[M, 2048] @ Bt[N, 2048]^T + bias
// Exact R5/R10 schedule: CTA 128x128, BK=64 (128B fp16 rows), 3-stage
// cp.async, 8 warps (2x4, 64x32 warp tile), 2 CTAs/SM. Single-pass fp16
// (10-bit mantissa = tf32 precision, half the MMA instructions).
// ROPE=true: fused bias + RoPE + bf16-split epilogue -> g_qb/g_kb/g_vhb/g_vlb.
// ROPE=false: bias epilogue -> fp32 C.
// ---------------------------------------------------------------------------
#define GEMM_SMEM (3 * 32768)

template<bool ROPE>
__global__ __launch_bounds__(256, 2)
void gemm_f16(int N,
              const __half* __restrict__ A,
              const __half* __restrict__ Bt,
              const float* __restrict__ bias,
              float* __restrict__ C) {
    extern __shared__ char sm[];
    const int tid = threadIdx.x;
    const int wid = tid >> 5;
    const int lid = tid & 31;
    const int M0 = blockIdx.y * 128;
    const int N0 = blockIdx.x * 128;
    const uint32_t sbase = smem_u32(sm);

    const int lrow  = tid >> 1;
    const int lhalf = (tid & 1) * 64;
    const uint32_t soff = (uint32_t)lrow * 128u + (uint32_t)lhalf;
    const char* Ag = (const char*)(A  + (size_t)(M0 + lrow) * KDIM) + lhalf;
    const char* Bg = (const char*)(Bt + (size_t)(N0 + lrow) * KDIM) + lhalf;

    const int wm = (wid & 1) * 64;
    const int wn = (wid >> 1) * 32;
    const int a_r  = wm + (lid & 15);
    const int a_cb = (lid >> 4) * 16;
    const int b_r  = wn + (lid & 7) + ((lid >> 4) << 3);
    const int b_cb = ((lid >> 3) & 1) * 16;

    float acc[4][4][4];
#pragma unroll
    for (int i = 0; i < 4; ++i)
#pragma unroll
        for (int j = 0; j < 4; ++j)
#pragma unroll
            for (int q = 0; q < 4; ++q) acc[i][j][q] = 0.0f;

#pragma unroll
    for (int s = 0; s < 2; ++s) {
        uint32_t ab = sbase + s * 32768u;
        uint32_t bb = ab + 16384u;
        const char* ag = Ag + s * 128;
        const char* bg = Bg + s * 128;
#pragma unroll
        for (int i = 0; i < 4; ++i) {
            cp16(ab + sw128(soff + i * 16), ag + i * 16);
            cp16(bb + sw128(soff + i * 16), bg + i * 16);
        }
        cp_commit();
    }

#pragma unroll 1
    for (int it = 0; it < NIT_H; ++it) {
        if (it + 1 < NIT_H) asm volatile("cp.async.wait_group 1;" ::: "memory");
        else                asm volatile("cp.async.wait_group 0;" ::: "memory");
        __syncthreads();

        if (it + 2 < NIT_H) {
            int s1 = (it + 2) % 3;
            uint32_t ab = sbase + s1 * 32768u;
            uint32_t bb = ab + 16384u;
            const char* ag = Ag + (size_t)(it + 2) * 128;
            const char* bg = Bg + (size_t)(it + 2) * 128;
#pragma unroll
            for (int i = 0; i < 4; ++i) {
                cp16(ab + sw128(soff + i * 16), ag + i * 16);
                cp16(bb + sw128(soff + i * 16), bg + i * 16);
            }
            cp_commit();
        }

        const int s = it % 3;
        const uint32_t ab = sbase + s * 32768u;
        const uint32_t bb = ab + 16384u;

#pragma unroll
        for (int kk = 0; kk < 4; ++kk) {
            uint32_t Ar[4][4];
            uint32_t Br[2][4];
#pragma unroll
            for (int i = 0; i < 4; ++i)
                LDSM4(Ar[i], ab + sw128((uint32_t)(a_r + i * 16) * 128u + kk * 32 + a_cb));
#pragma unroll
            for (int j2 = 0; j2 < 2; ++j2)
                LDSM4(Br[j2], bb + sw128((uint32_t)(b_r + j2 * 16) * 128u + kk * 32 + b_cb));
#pragma unroll
            for (int i = 0; i < 4; ++i)
#pragma unroll
                for (int j = 0; j < 4; ++j)
                    mma_f16(acc[i][j], Ar[i], Br[j >> 1][(j & 1) * 2], Br[j >> 1][(j & 1) * 2 + 1]);
        }
    }

    const int fr = lid >> 2;
    const int fc = (lid & 3) * 2;

    if (!ROPE) {
#pragma unroll
        for (int j = 0; j < 4; ++j) {
            const int col = N0 + wn + j * 8 + fc;
            const float bx = bias[col];
            const float by = bias[col + 1];
#pragma unroll
            for (int i = 0; i < 4; ++i) {
                const int row = M0 + wm + i * 16 + fr;
                float2 v0 = make_float2(acc[i][j][0] + bx, acc[i][j][1] + by);
                float2 v1 = make_float2(acc[i][j][2] + bx, acc[i][j][3] + by);
                *reinterpret_cast<float2*>(C + (size_t)row * N + col) = v0;
                *reinterpret_cast<float2*>(C + (size_t)(row + 8) * N + col) = v1;
            }
        }
        return;
    }

    // ---- fused RoPE/split epilogue ----
    __syncthreads();
    float* Cs = reinterpret_cast<float*>(sm);   // 128 x 129 fp32 staging (66KB)

#pragma unroll
    for (int j = 0; j < 4; ++j) {
        const int lc = wn + j * 8 + fc;
        const float bx = bias[N0 + lc];
        const float by = bias[N0 + lc + 1];
#pragma unroll
        for (int i = 0; i < 4; ++i) {
            const int lr = wm + i * 16 + fr;
            Cs[lr * 129 + lc]           = acc[i][j][0] + bx;
            Cs[lr * 129 + lc + 1]       = acc[i][j][1] + by;
            Cs[(lr + 8) * 129 + lc]     = acc[i][j][2] + bx;
            Cs[(lr + 8) * 129 + lc + 1] = acc[i][j][3] + by;
        }
    }
    __syncthreads();

    const int row = tid & 127;
    const int head = tid >> 7;
    const int mg = M0 + row;
    const int srow = mg >> 1;
    const int b = mg & 1;
    const int sec = N0 >> 11;          // 0=Q, 1=K, 2=V
    const int hg = ((N0 & 2047) >> 6) + head;
    const float* xs = Cs + row * 129 + head * 64;

    size_t o = ((size_t)(b * HEADS + hg) * S_LEN + srow) * HDIM;

    if (sec < 2) {
        __nv_bfloat16* outp = (sec == 0) ? g_qb : g_kb;
        const float qscale = (sec == 0) ? 0.125f : 1.0f;
#pragma unroll
        for (int ha = 0; ha < 2; ++ha) {
            const int d0 = ha * 16;
            float xl[16], xh[16];
#pragma unroll
            for (int i = 0; i < 16; ++i) {
                xl[i] = xs[d0 + i];
                xh[i] = xs[d0 + 32 + i];
            }
#pragma unroll
            for (int i = 0; i < 16; ++i) {
                float invf = __expf(-0.28782252f * (float)(d0 + i));
                float sn, cs;
                sincosf((float)srow * invf, &sn, &cs);
                float a0 = xl[i], a1 = xh[i];
                xl[i] = (a0 * cs - a1 * sn) * qscale;
                xh[i] = (a1 * cs + a0 * sn) * qscale;
            }
            uint32_t pk[8];
#pragma unroll
            for (int i = 0; i < 8; ++i) pk[i] = packb(xl[2 * i], xl[2 * i + 1]);
            uint4* dl = reinterpret_cast<uint4*>(outp + o + d0);
            dl[0] = make_uint4(pk[0], pk[1], pk[2], pk[3]);
            dl[1] = make_uint4(pk[4], pk[5], pk[6], pk[7]);
#pragma unroll
            for (int i = 0; i < 8; ++i) pk[i] = packb(xh[2 * i], xh[2 * i + 1]);
            uint4* dh = reinterpret_cast<uint4*>(outp + o + d0 + 32);
            dh[0] = make_uint4(pk[0], pk[1], pk[2], pk[3]);
            dh[1] = make_uint4(pk[4], pk[5], pk[6], pk[7]);
        }
    } else {
#pragma unroll
        for (int qa = 0; qa < 4; ++qa) {
            const int d0 = qa * 16;
            float xv[16];
#pragma unroll
            for (int i = 0; i < 16; ++i) xv[i] = xs[d0 + i];
            uint32_t ph[8], pl[8];
#pragma unroll
            for (int i = 0; i < 8; ++i) {
                float r0, r1;
                ph[i] = packlo(xv[2 * i], xv[2 * i + 1], r0, r1);
                pl[i] = packb(r0, r1);
            }
            uint4* dh = reinterpret_cast<uint4*>(g_vhb + o + d0);
            dh[0] = make_uint4(ph[0], ph[1], ph[2], ph[3]);
            dh[1] = make_uint4(ph[4], ph[5], ph[6], ph[7]);
            uint4* dl = reinterpret_cast<uint4*>(g_vlb + o + d0);
            dl[0] = make_uint4(pl[0], pl[1], pl[2], pl[3]);
            dl[1] = make_uint4(pl[4], pl[5], pl[6], pl[7]);
        }
    }
}

// ---------------------------------------------------------------------------
// Weight transpose + fp16 convert: fp32 [2048, Ncols] -> fp16 [Ncols, 2048]
// ---------------------------------------------------------------------------
__global__ __launch_bounds__(1024)
void transpose_kernel(const float* __restrict__ src, __half* __restrict__ dst, int Ncols) {
    __shared__ float tile[32][33];
    const int k0 = blockIdx.y * 32;
    const int n0 = blockIdx.x * 32;
    const int tx = threadIdx.x;
    const int ty = threadIdx.y;
    tile[ty][tx] = src[(size_t)(k0 + ty) * Ncols + n0 + tx];
    __syncthreads();
    dst[(size_t)(n0 + ty) * KDIM + k0 + tx] = __float2half_rn(tile[tx][ty]);
}

// hs fp32 -> fp16
__global__ __launch_bounds__(256)
void convH_kernel(const float* __restrict__ src, __half* __restrict__ dst) {
    size_t i = ((size_t)blockIdx.x * 256 + threadIdx.x) * 4;
    float4 v = *reinterpret_cast<const float4*>(src + i);
    __half2 h0 = __floats2half2_rn(v.x, v.y);
    __half2 h1 = __floats2half2_rn(v.z, v.w);
    *reinterpret_cast<__half2*>(dst + i)     = h0;
    *reinterpret_cast<__half2*>(dst + i + 2) = h1;
}

// ---------------------------------------------------------------------------
// HMMA flash attention (R10 numerics; ctx stored as fp16)
// ---------------------------------------------------------------------------
#define ATTN_SMEM 65536

__global__ __launch_bounds__(256, 2)
void attn_kernel() {
    extern __shared__ char smc[];
    const uint32_t sQ = smem_u32(smc);

    const int bh = blockIdx.y;
    const int qt = 15 - (int)blockIdx.x;
    const int q0 = qt * 128;
    const int t  = threadIdx.x;
    const int w  = t >> 5;
    const int lid = t & 31;

    const __nv_bfloat16* Qg  = g_qb  + (size_t)bh * S_LEN * HDIM;
    const __nv_bfloat16* Kg  = g_kb  + (size_t)bh * S_LEN * HDIM;
    const __nv_bfloat16* Vhg = g_vhb + (size_t)bh * S_LEN * HDIM;
    const __nv_bfloat16* Vlg = g_vlb + (size_t)bh * S_LEN * HDIM;

    {
        const int row = t >> 1;
        const int half = (t & 1) * 64;
        const char* src = (const char*)(Qg + (size_t)(q0 + row) * HDIM) + half;
#pragma unroll
        for (int i = 0; i < 4; ++i)
            cp16(sQ + sw128((uint32_t)row * 128u + half + i * 16), src + i * 16);
    }
    {
        const int row = t >> 2;
        const int qo = (t & 3) * 32;
        const uint32_t so = sw128((uint32_t)row * 128u + qo);
        const uint32_t so2 = sw128((uint32_t)row * 128u + qo + 16);
        const char* kg = (const char*)(Kg + (size_t)row * HDIM) + qo;
        const char* vh = (const char*)(Vhg + (size_t)row * HDIM) + qo;
        const char* vl = (const char*)(Vlg + (size_t)row * HDIM) + qo;
        uint32_t bK = sQ + 16384u;
        cp16(bK + so, kg);           cp16(bK + so2, kg + 16);
        cp16(bK + 8192u + so, vh);   cp16(bK + 8192u + so2, vh + 16);
        cp16(bK + 16384u + so, vl);  cp16(bK + 16384u + so2, vl + 16);
    }
    cp_commit();

    float oc[8][4];
#pragma unroll
    for (int jn = 0; jn < 8; ++jn)
#pragma unroll
        for (int q = 0; q < 4; ++q) oc[jn][q] = 0.0f;
    float m[2] = {-1e30f, -1e30f};
    float l[2] = {0.0f, 0.0f};

    const int nkt = 2 * qt + 2;
#pragma unroll 1
    for (int kt = 0; kt < nkt; ++kt) {
        if (kt + 1 < nkt) {
            const int k1 = (kt + 1) * 64;
            const int row = t >> 2;
            const int qo = (t & 3) * 32;
            const uint32_t so = sw128((uint32_t)row * 128u + qo);
            const uint32_t so2 = sw128((uint32_t)row * 128u + qo + 16);
            const char* kg = (const char*)(Kg + (size_t)(k1 + row) * HDIM) + qo;
            const char* vh = (const char*)(Vhg + (size_t)(k1 + row) * HDIM) + qo;
            const char* vl = (const char*)(Vlg + (size_t)(k1 + row) * HDIM) + qo;
            uint32_t bK = sQ + 16384u + ((kt + 1) & 1) * 24576u;
            cp16(bK + so, kg);           cp16(bK + so2, kg + 16);
            cp16(bK + 8192u + so, vh);   cp16(bK + 8192u + so2, vh + 16);
            cp16(bK + 16384u + so, vl);  cp16(bK + 16384u + so2, vl + 16);
            cp_commit();
            asm volatile("cp.async.wait_group 1;" ::: "memory");
        } else {
            asm volatile("cp.async.wait_group 0;" ::: "memory");
        }
        __syncthreads();

        const uint32_t bK  = sQ + 16384u + (kt & 1) * 24576u;
        const uint32_t bVh = bK + 8192u;
        const uint32_t bVl = bK + 16384u;
        const int k0 = kt * 64;

        float sc[8][4];
#pragma unroll
        for (int jn = 0; jn < 8; ++jn)
#pragma unroll
            for (int q = 0; q < 4; ++q) sc[jn][q] = 0.0f;

#pragma unroll
        for (int k4 = 0; k4 < 4; ++k4) {
            uint32_t QA[4];
            LDSM4(QA, sQ + sw128((uint32_t)(w * 16 + (lid & 15)) * 128u + k4 * 32 + (lid >> 4) * 16));
#pragma unroll
            for (int j2 = 0; j2 < 4; ++j2) {
                uint32_t KB[4];
                LDSM4(KB, bK + sw128((uint32_t)((lid & 7) + ((lid >> 4) << 3) + j2 * 16) * 128u
                                     + k4 * 32 + ((lid >> 3) & 1) * 16));
                mma_bf16(sc[j2 * 2 + 0], QA, KB[0], KB[1]);
                mma_bf16(sc[j2 * 2 + 1], QA, KB[2], KB[3]);
            }
        }

        if (k0 + 63 > q0 + w * 16) {
            const int rlo = q0 + w * 16 + (lid >> 2);
#pragma unroll
            for (int jn = 0; jn < 8; ++jn) {
                const int cb = k0 + jn * 8 + (lid & 3) * 2;
#pragma unroll
                for (int q = 0; q < 4; ++q) {
                    const int colg = cb + (q & 1);
                    const int rowg = rlo + (q >> 1) * 8;
                    if (colg > rowg) sc[jn][q] += MASK_NEG;
                }
            }
        }

#pragma unroll
        for (int hh = 0; hh < 2; ++hh) {
            float mt = sc[0][hh * 2];
#pragma unroll
            for (int jn = 0; jn < 8; ++jn)
                mt = fmaxf(mt, fmaxf(sc[jn][hh * 2], sc[jn][hh * 2 + 1]));
            mt = fmaxf(mt, __shfl_xor_sync(0xffffffffu, mt, 1));
            mt = fmaxf(mt, __shfl_xor_sync(0xffffffffu, mt, 2));

            const float mn = fmaxf(m[hh], mt);
            const float corr = __expf(m[hh] - mn);
            float ps = 0.0f;
#pragma unroll
            for (int jn = 0; jn < 8; ++jn) {
                float p0 = __expf(sc[jn][hh * 2] - mn);
                float p1 = __expf(sc[jn][hh * 2 + 1] - mn);
                sc[jn][hh * 2] = p0;
                sc[jn][hh * 2 + 1] = p1;
                ps += p0 + p1;
            }
            ps += __shfl_xor_sync(0xffffffffu, ps, 1);
            ps += __shfl_xor_sync(0xffffffffu, ps, 2);
            l[hh] = l[hh] * corr + ps;
            m[hh] = mn;
#pragma unroll
            for (int jn = 0; jn < 8; ++jn) {
                oc[jn][hh * 2] *= corr;
                oc[jn][hh * 2 + 1] *= corr;
            }
        }

#pragma unroll
        for (int k4 = 0; k4 < 4; ++k4) {
            uint32_t PhA[4], PlA[4];
            {
                float r0, r1, r2, r3, r4, r5, r6, r7;
                PhA[0] = packlo(sc[2 * k4][0], sc[2 * k4][1], r0, r1);
                PhA[1] = packlo(sc[2 * k4][2], sc[2 * k4][3], r2, r3);
                PhA[2] = packlo(sc[2 * k4 + 1][0], sc[2 * k4 + 1][1], r4, r5);
                PhA[3] = packlo(sc[2 * k4 + 1][2], sc[2 * k4 + 1][3], r6, r7);
                PlA[0] = packb(r0, r1);
                PlA[1] = packb(r2, r3);
                PlA[2] = packb(r4, r5);
                PlA[3] = packb(r6, r7);
            }
#pragma unroll
            for (int j2 = 0; j2 < 4; ++j2) {
                uint32_t VhB[4], VlB[4];
                LDSM4T(VhB, bVh + sw128((uint32_t)(k4 * 16 + (lid & 15)) * 128u + j2 * 32 + (lid >> 4) * 16));
                LDSM4T(VlB, bVl + sw128((uint32_t)(k4 * 16 + (lid & 15)) * 128u + j2 * 32 + (lid >> 4) * 16));
                mma_bf16(oc[j2 * 2 + 0], PhA, VhB[0], VhB[1]);
                mma_bf16(oc[j2 * 2 + 1], PhA, VhB[2], VhB[3]);
                mma_bf16(oc[j2 * 2 + 0], PhA, VlB[0], VlB[1]);
                mma_bf16(oc[j2 * 2 + 1], PhA, VlB[2], VlB[3]);
                mma_bf16(oc[j2 * 2 + 0], PlA, VhB[0], VhB[1]);
                mma_bf16(oc[j2 * 2 + 1], PlA, VhB[2], VhB[3]);
            }
        }
        __syncthreads();
    }

    // epilogue: normalize, write ctx as fp16
    const int b = bh >> 5;
    const int h = bh & 31;
#pragma unroll
    for (int hh = 0; hh < 2; ++hh) {
        const int row = q0 + w * 16 + (lid >> 2) + hh * 8;
        const float invl = 1.0f / l[hh];
        __half* dst = g_ctx + (size_t)(row * BATCH + b) * EMB + h * HDIM;
#pragma unroll
        for (int jn = 0; jn < 8; ++jn) {
            __half2 v = __floats2half2_rn(oc[jn][hh * 2] * invl, oc[jn][hh * 2 + 1] * invl);
            *reinterpret_cast<__half2*>(dst + jn * 8 + (lid & 3) * 2) = v;
        }
    }
}

// ---------------------------------------------------------------------------
// Launch
// ---------------------------------------------------------------------------
extern "C" void kernel_launch(void* const* d_in, const int* in_sizes, int n_in,
                              void* d_out, int out_size) {
    const float* hs    = (const float*)d_in[0];
    const float* qkv_w = (const float*)d_in[1];
    const float* qkv_b = (const float*)d_in[2];
    const float* out_w = (const float*)d_in[3];
    const float* out_b = (const float*)d_in[4];
    float* out = (float*)d_out;

    cudaFuncSetAttribute(gemm_f16<true>,  cudaFuncAttributeMaxDynamicSharedMemorySize, GEMM_SMEM);
    cudaFuncSetAttribute(gemm_f16<false>, cudaFuncAttributeMaxDynamicSharedMemorySize, GEMM_SMEM);
    cudaFuncSetAttribute(attn_kernel, cudaFuncAttributeMaxDynamicSharedMemorySize, ATTN_SMEM);

    __half *ctx, *hsh, *Btq, *Bto;
    cudaGetSymbolAddress((void**)&ctx, g_ctx);
    cudaGetSymbolAddress((void**)&hsh, g_hsh);
    cudaGetSymbolAddress((void**)&Btq, g_Btq);
    cudaGetSymbolAddress((void**)&Bto, g_Bto);

    // Weight transposes (fp16 convert fused)
    {
        dim3 blk(32, 32);
        transpose_kernel<<<dim3(QKV_N / 32, KDIM / 32), blk>>>(qkv_w, Btq, QKV_N);
        transpose_kernel<<<dim3(EMB / 32, KDIM / 32), blk>>>(out_w, Bto, EMB);
    }
    // hs -> fp16
    convH_kernel<<<(MROWS * EMB) / 1024, 256>>>(hs, hsh);

    // 1. QKV projection (fp16 HMMA) with fused bias + RoPE + bf16-split epilogue
    gemm_f16<true><<<dim3(QKV_N / 128, MROWS / 128), 256, GEMM_SMEM>>>(
        QKV_N, hsh, Btq, qkv_b, nullptr);

    // 2. Causal attention (HMMA flash); ctx written as fp16
    attn_kernel<<<dim3(S_LEN / 128, BATCH * HEADS), 256, ATTN_SMEM>>>();

    // 3. Output projection (fp16 HMMA)
    gemm_f16<false><<<dim3(EMB / 128, MROWS / 128), 256, GEMM_SMEM>>>(
        EMB, ctx, Bto, out_b, out);
}

// round 17
// speedup vs baseline: 1.9529x; 1.1364x over previous
#include <cuda_runtime.h>
#include <cuda_fp16.h>
#include <math.h>
#include <stdint.h>

// Problem constants
#define S_LEN 2048
#define BATCH 2
#define EMB   2048
#define HEADS 32
#define HDIM  64
#define MROWS (S_LEN * BATCH)          // 4096
#define QKV_N (3 * EMB)                // 6144
#define KDIM  2048
#define NIT_H 32                       // 2048 / 64 (BK=64 fp16)
#define MASK_NEG (-66504.0f)

// ---------------------------------------------------------------------------
// Scratch (static device globals)
// ---------------------------------------------------------------------------
__device__ __half g_ctx[(size_t)MROWS * EMB];                  // attention out, fp16
__device__ __half g_hsh[(size_t)MROWS * EMB];                  // hs -> fp16

__device__ __half g_Btq[(size_t)QKV_N * KDIM];                 // qkv_w^T fp16
__device__ __half g_Bto[(size_t)EMB   * KDIM];                 // out_w^T fp16

#define QKVLEN ((size_t)BATCH * HEADS * S_LEN * HDIM)
__device__ __half g_qh[QKVLEN];   // rope(Q) * 0.125, fp16
__device__ __half g_kh[QKVLEN];   // rope(K), fp16
__device__ __half g_vh[QKVLEN];   // V, fp16

// ---------------------------------------------------------------------------
// Helpers (sm_80-era PTX — legal at compute_103)
// ---------------------------------------------------------------------------
__device__ __forceinline__ uint32_t smem_u32(const void* p) {
    uint32_t a;
    asm("{ .reg .u64 t; cvta.to.shared.u64 t, %1; cvt.u32.u64 %0, t; }" : "=r"(a) : "l"(p));
    return a;
}
__device__ __forceinline__ void cp16(uint32_t saddr, const void* g) {
    asm volatile("cp.async.cg.shared.global [%0], [%1], 16;" :: "r"(saddr), "l"(g) : "memory");
}
__device__ __forceinline__ void cp_commit() {
    asm volatile("cp.async.commit_group;" ::: "memory");
}
__device__ __forceinline__ uint32_t sw128(uint32_t off) {
    return off ^ ((off >> 3) & 0x70);
}

#define LDSM4(r, addr) \
    asm volatile("ldmatrix.sync.aligned.m8n8.x4.shared.b16 {%0,%1,%2,%3}, [%4];" \
                 : "=r"((r)[0]), "=r"((r)[1]), "=r"((r)[2]), "=r"((r)[3]) : "r"(addr))

#define LDSM4T(r, addr) \
    asm volatile("ldmatrix.sync.aligned.m8n8.x4.trans.shared.b16 {%0,%1,%2,%3}, [%4];" \
                 : "=r"((r)[0]), "=r"((r)[1]), "=r"((r)[2]), "=r"((r)[3]) : "r"(addr))

__device__ __forceinline__ void mma_f16(float* d, const uint32_t* a, uint32_t b0, uint32_t b1) {
    asm volatile(
        "mma.sync.aligned.m16n8k16.row.col.f32.f16.f16.f32 "
        "{%0,%1,%2,%3}, {%4,%5,%6,%7}, {%8,%9}, {%0,%1,%2,%3};"
        : "+f"(d[0]), "+f"(d[1]), "+f"(d[2]), "+f"(d[3])
        : "r"(a[0]), "r"(a[1]), "r"(a[2]), "r"(a[3]), "r"(b0), "r"(b1));
}

__device__ __forceinline__ uint32_t packh(float a, float b) {
    __half2 h = __floats2half2_rn(a, b);
    return *reinterpret_cast<uint32_t*>(&h);
}

// ---------------------------------------------------------------------------
// FP16 HMMA GEMM:  C[M=4096, N] = A[M, 2048] @ Bt[N, 2048]^T + bias
// Proven schedule: CTA 128x128, BK=64 (128B fp16 rows), 3-stage cp.async,
// 8 warps (2x4, 64x32 warp tile), 2 CTAs/SM.
// ROPE=true: fused bias + RoPE + fp16 epilogue -> g_qh/g_kh/g_vh.
// ROPE=false: bias epilogue -> fp32 C.
// ---------------------------------------------------------------------------
#define GEMM_SMEM (3 * 32768)

template<bool ROPE>
__global__ __launch_bounds__(256, 2)
void gemm_f16(int N,
              const __half* __restrict__ A,
              const __half* __restrict__ Bt,
              const float* __restrict__ bias,
              float* __restrict__ C) {
    extern __shared__ char sm[];
    const int tid = threadIdx.x;
    const int wid = tid >> 5;
    const int lid = tid & 31;
    const int M0 = blockIdx.y * 128;
    const int N0 = blockIdx.x * 128;
    const uint32_t sbase = smem_u32(sm);

    const int lrow  = tid >> 1;
    const int lhalf = (tid & 1) * 64;
    const uint32_t soff = (uint32_t)lrow * 128u + (uint32_t)lhalf;
    const char* Ag = (const char*)(A  + (size_t)(M0 + lrow) * KDIM) + lhalf;
    const char* Bg = (const char*)(Bt + (size_t)(N0 + lrow) * KDIM) + lhalf;

    const int wm = (wid & 1) * 64;
    const int wn = (wid >> 1) * 32;
    const int a_r  = wm + (lid & 15);
    const int a_cb = (lid >> 4) * 16;
    const int b_r  = wn + (lid & 7) + ((lid >> 4) << 3);
    const int b_cb = ((lid >> 3) & 1) * 16;

    float acc[4][4][4];
#pragma unroll
    for (int i = 0; i < 4; ++i)
#pragma unroll
        for (int j = 0; j < 4; ++j)
#pragma unroll
            for (int q = 0; q < 4; ++q) acc[i][j][q] = 0.0f;

#pragma unroll
    for (int s = 0; s < 2; ++s) {
        uint32_t ab = sbase + s * 32768u;
        uint32_t bb = ab + 16384u;
        const char* ag = Ag + s * 128;
        const char* bg = Bg + s * 128;
#pragma unroll
        for (int i = 0; i < 4; ++i) {
            cp16(ab + sw128(soff + i * 16), ag + i * 16);
            cp16(bb + sw128(soff + i * 16), bg + i * 16);
        }
        cp_commit();
    }

#pragma unroll 1
    for (int it = 0; it < NIT_H; ++it) {
        if (it + 1 < NIT_H) asm volatile("cp.async.wait_group 1;" ::: "memory");
        else                asm volatile("cp.async.wait_group 0;" ::: "memory");
        __syncthreads();

        if (it + 2 < NIT_H) {
            int s1 = (it + 2) % 3;
            uint32_t ab = sbase + s1 * 32768u;
            uint32_t bb = ab + 16384u;
            const char* ag = Ag + (size_t)(it + 2) * 128;
            const char* bg = Bg + (size_t)(it + 2) * 128;
#pragma unroll
            for (int i = 0; i < 4; ++i) {
                cp16(ab + sw128(soff + i * 16), ag + i * 16);
                cp16(bb + sw128(soff + i * 16), bg + i * 16);
            }
            cp_commit();
        }

        const int s = it % 3;
        const uint32_t ab = sbase + s * 32768u;
        const uint32_t bb = ab + 16384u;

#pragma unroll
        for (int kk = 0; kk < 4; ++kk) {
            uint32_t Ar[4][4];
            uint32_t Br[2][4];
#pragma unroll
            for (int i = 0; i < 4; ++i)
                LDSM4(Ar[i], ab + sw128((uint32_t)(a_r + i * 16) * 128u + kk * 32 + a_cb));
#pragma unroll
            for (int j2 = 0; j2 < 2; ++j2)
                LDSM4(Br[j2], bb + sw128((uint32_t)(b_r + j2 * 16) * 128u + kk * 32 + b_cb));
#pragma unroll
            for (int i = 0; i < 4; ++i)
#pragma unroll
                for (int j = 0; j < 4; ++j)
                    mma_f16(acc[i][j], Ar[i], Br[j >> 1][(j & 1) * 2], Br[j >> 1][(j & 1) * 2 + 1]);
        }
    }

    const int fr = lid >> 2;
    const int fc = (lid & 3) * 2;

    if (!ROPE) {
#pragma unroll
        for (int j = 0; j < 4; ++j) {
            const int col = N0 + wn + j * 8 + fc;
            const float bx = bias[col];
            const float by = bias[col + 1];
#pragma unroll
            for (int i = 0; i < 4; ++i) {
                const int row = M0 + wm + i * 16 + fr;
                float2 v0 = make_float2(acc[i][j][0] + bx, acc[i][j][1] + by);
                float2 v1 = make_float2(acc[i][j][2] + bx, acc[i][j][3] + by);
                *reinterpret_cast<float2*>(C + (size_t)row * N + col) = v0;
                *reinterpret_cast<float2*>(C + (size_t)(row + 8) * N + col) = v1;
            }
        }
        return;
    }

    // ---- fused RoPE/split epilogue ----
    __syncthreads();
    float* Cs = reinterpret_cast<float*>(sm);   // 128 x 129 fp32 staging

#pragma unroll
    for (int j = 0; j < 4; ++j) {
        const int lc = wn + j * 8 + fc;
        const float bx = bias[N0 + lc];
        const float by = bias[N0 + lc + 1];
#pragma unroll
        for (int i = 0; i < 4; ++i) {
            const int lr = wm + i * 16 + fr;
            Cs[lr * 129 + lc]           = acc[i][j][0] + bx;
            Cs[lr * 129 + lc + 1]       = acc[i][j][1] + by;
            Cs[(lr + 8) * 129 + lc]     = acc[i][j][2] + bx;
            Cs[(lr + 8) * 129 + lc + 1] = acc[i][j][3] + by;
        }
    }
    __syncthreads();

    const int row = tid & 127;
    const int head = tid >> 7;
    const int mg = M0 + row;
    const int srow = mg >> 1;
    const int b = mg & 1;
    const int sec = N0 >> 11;          // 0=Q, 1=K, 2=V
    const int hg = ((N0 & 2047) >> 6) + head;
    const float* xs = Cs + row * 129 + head * 64;

    size_t o = ((size_t)(b * HEADS + hg) * S_LEN + srow) * HDIM;

    if (sec < 2) {
        __half* outp = (sec == 0) ? g_qh : g_kh;
        const float qscale = (sec == 0) ? 0.125f : 1.0f;
#pragma unroll
        for (int ha = 0; ha < 2; ++ha) {
            const int d0 = ha * 16;
            float xl[16], xh[16];
#pragma unroll
            for (int i = 0; i < 16; ++i) {
                xl[i] = xs[d0 + i];
                xh[i] = xs[d0 + 32 + i];
            }
#pragma unroll
            for (int i = 0; i < 16; ++i) {
                float invf = __expf(-0.28782252f * (float)(d0 + i));
                float sn, cs;
                sincosf((float)srow * invf, &sn, &cs);
                float a0 = xl[i], a1 = xh[i];
                xl[i] = (a0 * cs - a1 * sn) * qscale;
                xh[i] = (a1 * cs + a0 * sn) * qscale;
            }
            uint32_t pk[8];
#pragma unroll
            for (int i = 0; i < 8; ++i) pk[i] = packh(xl[2 * i], xl[2 * i + 1]);
            uint4* dl = reinterpret_cast<uint4*>(outp + o + d0);
            dl[0] = make_uint4(pk[0], pk[1], pk[2], pk[3]);
            dl[1] = make_uint4(pk[4], pk[5], pk[6], pk[7]);
#pragma unroll
            for (int i = 0; i < 8; ++i) pk[i] = packh(xh[2 * i], xh[2 * i + 1]);
            uint4* dh = reinterpret_cast<uint4*>(outp + o + d0 + 32);
            dh[0] = make_uint4(pk[0], pk[1], pk[2], pk[3]);
            dh[1] = make_uint4(pk[4], pk[5], pk[6], pk[7]);
        }
    } else {
        // V: plain fp16 convert
#pragma unroll
        for (int qa = 0; qa < 4; ++qa) {
            const int d0 = qa * 16;
            uint32_t pk[8];
#pragma unroll
            for (int i = 0; i < 8; ++i)
                pk[i] = packh(xs[d0 + 2 * i], xs[d0 + 2 * i + 1]);
            uint4* dv = reinterpret_cast<uint4*>(g_vh + o + d0);
            dv[0] = make_uint4(pk[0], pk[1], pk[2], pk[3]);
            dv[1] = make_uint4(pk[4], pk[5], pk[6], pk[7]);
        }
    }
}

// ---------------------------------------------------------------------------
// Weight transpose + fp16 convert: fp32 [2048, Ncols] -> fp16 [Ncols, 2048]
// ---------------------------------------------------------------------------
__global__ __launch_bounds__(1024)
void transpose_kernel(const float* __restrict__ src, __half* __restrict__ dst, int Ncols) {
    __shared__ float tile[32][33];
    const int k0 = blockIdx.y * 32;
    const int n0 = blockIdx.x * 32;
    const int tx = threadIdx.x;
    const int ty = threadIdx.y;
    tile[ty][tx] = src[(size_t)(k0 + ty) * Ncols + n0 + tx];
    __syncthreads();
    dst[(size_t)(n0 + ty) * KDIM + k0 + tx] = __float2half_rn(tile[tx][ty]);
}

// hs fp32 -> fp16
__global__ __launch_bounds__(256)
void convH_kernel(const float* __restrict__ src, __half* __restrict__ dst) {
    size_t i = ((size_t)blockIdx.x * 256 + threadIdx.x) * 4;
    float4 v = *reinterpret_cast<const float4*>(src + i);
    __half2 h0 = __floats2half2_rn(v.x, v.y);
    __half2 h1 = __floats2half2_rn(v.z, v.w);
    *reinterpret_cast<__half2*>(dst + i)     = h0;
    *reinterpret_cast<__half2*>(dst + i + 2) = h1;
}

// ---------------------------------------------------------------------------
// FP16 HMMA flash attention. Grid (16, B*H), 256 threads = 8 warps.
// Warp w owns query rows [w*16, w*16+16). 64-key tiles, double-buffered
// cp.async (K, V). QK fp16 single-pass; P packed to fp16 in registers
// (C-frag == A-frag identity); PV fp16 single-pass. V^T via ldmatrix.trans.
// smem 48KB: Q 16KB + 2 x (K 8KB + V 8KB). 2 CTAs/SM.
// ---------------------------------------------------------------------------
#define ATTN_SMEM 49152

__global__ __launch_bounds__(256, 2)
void attn_kernel() {
    extern __shared__ char smc[];
    const uint32_t sQ = smem_u32(smc);

    const int bh = blockIdx.y;
    const int qt = 15 - (int)blockIdx.x;      // longest-first
    const int q0 = qt * 128;
    const int t  = threadIdx.x;
    const int w  = t >> 5;
    const int lid = t & 31;

    const __half* Qg = g_qh + (size_t)bh * S_LEN * HDIM;
    const __half* Kg = g_kh + (size_t)bh * S_LEN * HDIM;
    const __half* Vg = g_vh + (size_t)bh * S_LEN * HDIM;

    // prologue: Q tile + key-tile 0 into buffer 0
    {
        const int row = t >> 1;
        const int half = (t & 1) * 64;
        const char* src = (const char*)(Qg + (size_t)(q0 + row) * HDIM) + half;
#pragma unroll
        for (int i = 0; i < 4; ++i)
            cp16(sQ + sw128((uint32_t)row * 128u + half + i * 16), src + i * 16);
    }
    {
        const int row = t >> 2;
        const int qo = (t & 3) * 32;
        const uint32_t so = sw128((uint32_t)row * 128u + qo);
        const uint32_t so2 = sw128((uint32_t)row * 128u + qo + 16);
        const char* kg = (const char*)(Kg + (size_t)row * HDIM) + qo;
        const char* vg = (const char*)(Vg + (size_t)row * HDIM) + qo;
        uint32_t bK = sQ + 16384u;
        cp16(bK + so, kg);          cp16(bK + so2, kg + 16);
        cp16(bK + 8192u + so, vg);  cp16(bK + 8192u + so2, vg + 16);
    }
    cp_commit();

    float oc[8][4];
#pragma unroll
    for (int jn = 0; jn < 8; ++jn)
#pragma unroll
        for (int q = 0; q < 4; ++q) oc[jn][q] = 0.0f;
    float m[2] = {-1e30f, -1e30f};
    float l[2] = {0.0f, 0.0f};

    const int nkt = 2 * qt + 2;
#pragma unroll 1
    for (int kt = 0; kt < nkt; ++kt) {
        if (kt + 1 < nkt) {
            const int k1 = (kt + 1) * 64;
            const int row = t >> 2;
            const int qo = (t & 3) * 32;
            const uint32_t so = sw128((uint32_t)row * 128u + qo);
            const uint32_t so2 = sw128((uint32_t)row * 128u + qo + 16);
            const char* kg = (const char*)(Kg + (size_t)(k1 + row) * HDIM) + qo;
            const char* vg = (const char*)(Vg + (size_t)(k1 + row) * HDIM) + qo;
            uint32_t bK = sQ + 16384u + ((kt + 1) & 1) * 16384u;
            cp16(bK + so, kg);          cp16(bK + so2, kg + 16);
            cp16(bK + 8192u + so, vg);  cp16(bK + 8192u + so2, vg + 16);
            cp_commit();
            asm volatile("cp.async.wait_group 1;" ::: "memory");
        } else {
            asm volatile("cp.async.wait_group 0;" ::: "memory");
        }
        __syncthreads();

        const uint32_t bK = sQ + 16384u + (kt & 1) * 16384u;
        const uint32_t bV = bK + 8192u;
        const int k0 = kt * 64;

        // ---- QK: m16 x n64 per warp, fp16 ----
        float sc[8][4];
#pragma unroll
        for (int jn = 0; jn < 8; ++jn)
#pragma unroll
            for (int q = 0; q < 4; ++q) sc[jn][q] = 0.0f;

#pragma unroll
        for (int k4 = 0; k4 < 4; ++k4) {
            uint32_t QA[4];
            LDSM4(QA, sQ + sw128((uint32_t)(w * 16 + (lid & 15)) * 128u + k4 * 32 + (lid >> 4) * 16));
#pragma unroll
            for (int j2 = 0; j2 < 4; ++j2) {
                uint32_t KB[4];
                LDSM4(KB, bK + sw128((uint32_t)((lid & 7) + ((lid >> 4) << 3) + j2 * 16) * 128u
                                     + k4 * 32 + ((lid >> 3) & 1) * 16));
                mma_f16(sc[j2 * 2 + 0], QA, KB[0], KB[1]);
                mma_f16(sc[j2 * 2 + 1], QA, KB[2], KB[3]);
            }
        }

        // ---- causal mask ----
        if (k0 + 63 > q0 + w * 16) {
            const int rlo = q0 + w * 16 + (lid >> 2);
#pragma unroll
            for (int jn = 0; jn < 8; ++jn) {
                const int cb = k0 + jn * 8 + (lid & 3) * 2;
#pragma unroll
                for (int q = 0; q < 4; ++q) {
                    const int colg = cb + (q & 1);
                    const int rowg = rlo + (q >> 1) * 8;
                    if (colg > rowg) sc[jn][q] += MASK_NEG;
                }
            }
        }

        // ---- online softmax per row-half ----
#pragma unroll
        for (int hh = 0; hh < 2; ++hh) {
            float mt = sc[0][hh * 2];
#pragma unroll
            for (int jn = 0; jn < 8; ++jn)
                mt = fmaxf(mt, fmaxf(sc[jn][hh * 2], sc[jn][hh * 2 + 1]));
            mt = fmaxf(mt, __shfl_xor_sync(0xffffffffu, mt, 1));
            mt = fmaxf(mt, __shfl_xor_sync(0xffffffffu, mt, 2));

            const float mn = fmaxf(m[hh], mt);
            const float corr = __expf(m[hh] - mn);
            float ps = 0.0f;
#pragma unroll
            for (int jn = 0; jn < 8; ++jn) {
                float p0 = __expf(sc[jn][hh * 2] - mn);
                float p1 = __expf(sc[jn][hh * 2 + 1] - mn);
                sc[jn][hh * 2] = p0;
                sc[jn][hh * 2 + 1] = p1;
                ps += p0 + p1;
            }
            ps += __shfl_xor_sync(0xffffffffu, ps, 1);
            ps += __shfl_xor_sync(0xffffffffu, ps, 2);
            l[hh] = l[hh] * corr + ps;
            m[hh] = mn;
#pragma unroll
            for (int jn = 0; jn < 8; ++jn) {
                oc[jn][hh * 2] *= corr;
                oc[jn][hh * 2 + 1] *= corr;
            }
        }

        // ---- PV: single-pass fp16, P in registers (C-frag == A-frag) ----
#pragma unroll
        for (int k4 = 0; k4 < 4; ++k4) {
            uint32_t PA[4];
            PA[0] = packh(sc[2 * k4][0], sc[2 * k4][1]);
            PA[1] = packh(sc[2 * k4][2], sc[2 * k4][3]);
            PA[2] = packh(sc[2 * k4 + 1][0], sc[2 * k4 + 1][1]);
            PA[3] = packh(sc[2 * k4 + 1][2], sc[2 * k4 + 1][3]);
#pragma unroll
            for (int j2 = 0; j2 < 4; ++j2) {
                uint32_t VB[4];
                LDSM4T(VB, bV + sw128((uint32_t)(k4 * 16 + (lid & 15)) * 128u + j2 * 32 + (lid >> 4) * 16));
                mma_f16(oc[j2 * 2 + 0], PA, VB[0], VB[1]);
                mma_f16(oc[j2 * 2 + 1], PA, VB[2], VB[3]);
            }
        }
        __syncthreads();   // all warps done with this buffer before refill
    }

    // ---- epilogue: normalize, write ctx fp16 ----
    const int b = bh >> 5;
    const int h = bh & 31;
#pragma unroll
    for (int hh = 0; hh < 2; ++hh) {
        const int row = q0 + w * 16 + (lid >> 2) + hh * 8;
        const float invl = 1.0f / l[hh];
        __half* dst = g_ctx + (size_t)(row * BATCH + b) * EMB + h * HDIM;
#pragma unroll
        for (int jn = 0; jn < 8; ++jn) {
            __half2 v = __floats2half2_rn(oc[jn][hh * 2] * invl, oc[jn][hh * 2 + 1] * invl);
            *reinterpret_cast<__half2*>(dst + jn * 8 + (lid & 3) * 2) = v;
        }
    }
}

// ---------------------------------------------------------------------------
// Launch
// ---------------------------------------------------------------------------
extern "C" void kernel_launch(void* const* d_in, const int* in_sizes, int n_in,
                              void* d_out, int out_size) {
    const float* hs    = (const float*)d_in[0];
    const float* qkv_w = (const float*)d_in[1];
    const float* qkv_b = (const float*)d_in[2];
    const float* out_w = (const float*)d_in[3];
    const float* out_b = (const float*)d_in[4];
    float* out = (float*)d_out;

    cudaFuncSetAttribute(gemm_f16<true>,  cudaFuncAttributeMaxDynamicSharedMemorySize, GEMM_SMEM);
    cudaFuncSetAttribute(gemm_f16<false>, cudaFuncAttributeMaxDynamicSharedMemorySize, GEMM_SMEM);
    cudaFuncSetAttribute(attn_kernel, cudaFuncAttributeMaxDynamicSharedMemorySize, ATTN_SMEM);

    __half *ctx, *hsh, *Btq, *Bto;
    cudaGetSymbolAddress((void**)&ctx, g_ctx);
    cudaGetSymbolAddress((void**)&hsh, g_hsh);
    cudaGetSymbolAddress((void**)&Btq, g_Btq);
    cudaGetSymbolAddress((void**)&Bto, g_Bto);

    // Weight transposes (fp16 convert fused)
    {
        dim3 blk(32, 32);
        transpose_kernel<<<dim3(QKV_N / 32, KDIM / 32), blk>>>(qkv_w, Btq, QKV_N);
        transpose_kernel<<<dim3(EMB / 32, KDIM / 32), blk>>>(out_w, Bto, EMB);
    }
    // hs -> fp16
    convH_kernel<<<(MROWS * EMB) / 1024, 256>>>(hs, hsh);

    // 1. QKV projection (fp16 HMMA) with fused bias + RoPE + fp16 epilogue
    gemm_f16<true><<<dim3(QKV_N / 128, MROWS / 128), 256, GEMM_SMEM>>>(
        QKV_N, hsh, Btq, qkv_b, nullptr);

    // 2. Causal attention (fp16 HMMA flash); ctx written as fp16
    attn_kernel<<<dim3(S_LEN / 128, BATCH * HEADS), 256, ATTN_SMEM>>>();

    // 3. Output projection (fp16 HMMA)
    gemm_f16<false><<<dim3(EMB / 128, MROWS / 128), 256, GEMM_SMEM>>>(
        EMB, ctx, Bto, out_b, out);
}